// round 16
// baseline (speedup 1.0000x reference)
#include <cuda_runtime.h>

// out[i] = floorf(image[i] * 0.5f) — HBM-bound streaming. Final hint-matrix
// cell: PLAIN v8 accesses (no L2 eviction hints). Measured so far on the same
// shape: cs/cs 26.14us, evict_last/evict_first 25.57-26.05us, evict_first/
// evict_last 26.02us — all noise around the ~5.5TB/s DRAM rw ceiling
// (~143MB effective traffic/replay, invariant under hints).
//   - flat grid 6144 x 256, 2 x 256-bit (v8.b32) per thread, warp-coalesced
//   - 22 regs, ~75% occupancy, front-batched independent loads
// (Resubmission of R15 — previous round hit a container infra failure.)

#define V8PT 2  // 8-float (32B) vectors per thread
#define TPB  256

__device__ __forceinline__ void ld256(const float* p, unsigned* v) {
    asm volatile("ld.global.v8.b32 {%0,%1,%2,%3,%4,%5,%6,%7}, [%8];"
                 : "=r"(v[0]), "=r"(v[1]), "=r"(v[2]), "=r"(v[3]),
                   "=r"(v[4]), "=r"(v[5]), "=r"(v[6]), "=r"(v[7])
                 : "l"(p));
}

__device__ __forceinline__ void st256(float* p, const unsigned* v) {
    asm volatile("st.global.v8.b32 [%0], {%1,%2,%3,%4,%5,%6,%7,%8};"
                 :: "l"(p),
                    "r"(v[0]), "r"(v[1]), "r"(v[2]), "r"(v[3]),
                    "r"(v[4]), "r"(v[5]), "r"(v[6]), "r"(v[7])
                 : "memory");
}

__device__ __forceinline__ void halve8(unsigned* v) {
    #pragma unroll
    for (int j = 0; j < 8; j++) {
        float f = __uint_as_float(v[j]);
        v[j] = __float_as_uint(floorf(f * 0.5f));
    }
}

__global__ void __launch_bounds__(TPB) stego_halve_kernel(
    const float* __restrict__ in, float* __restrict__ out, int n8)
{
    int blockBase = blockIdx.x * (TPB * V8PT);   // in v8 units
    int t = threadIdx.x;

    if (blockBase + TPB * V8PT <= n8) {
        unsigned v[V8PT][8];
        #pragma unroll
        for (int k = 0; k < V8PT; k++)
            ld256(in + (size_t)(blockBase + t + k * TPB) * 8, v[k]);
        #pragma unroll
        for (int k = 0; k < V8PT; k++) {
            halve8(v[k]);
            st256(out + (size_t)(blockBase + t + k * TPB) * 8, v[k]);
        }
    } else {
        // tail (unused for n = 25,165,824, but safe)
        #pragma unroll
        for (int k = 0; k < V8PT; k++) {
            int i = blockBase + t + k * TPB;
            if (i < n8) {
                unsigned v[8];
                ld256(in + (size_t)i * 8, v);
                halve8(v);
                st256(out + (size_t)i * 8, v);
            }
        }
    }
}

extern "C" void kernel_launch(void* const* d_in, const int* in_sizes, int n_in,
                              void* d_out, int out_size)
{
    const float* img = (const float*)d_in[0];
    float* out = (float*)d_out;
    int n = in_sizes[0];                 // 25,165,824 — divisible by 8
    int n8 = n / 8;
    int elems_per_block = TPB * V8PT;
    int blocks = (n8 + elems_per_block - 1) / elems_per_block;
    stego_halve_kernel<<<blocks, TPB>>>(img, out, n8);
}

// round 17
// speedup vs baseline: 1.0082x; 1.0082x over previous
#include <cuda_runtime.h>

// out[i] = floorf(image[i] * 0.5f) — HBM-bound streaming. FINAL KERNEL.
// Best of 11 measured variants across all axes:
//   hint matrix on v8 shape: el/ef 25.57 & 26.05us (best, twice), ef/el 26.02,
//   cs/cs 26.14, none 26.50; float4 VPT=4 26.3; VPT=8 27.1 (occ drop);
//   persistent grid 27.4 (broke load batching); per-thread-contig 35.9.
// Pinned at the ~5.5TB/s achieved DRAM ceiling for a 50/50 rw stream
// (~143MB effective traffic/replay; issue 9%, fma 3% — nothing else binds).
// Config: flat grid 6144 x 256; 2 x 256-bit (v8.b32) warp-coalesced accesses
// per thread (t + k*TPB); L2::evict_last loads + L2::evict_first stores;
// 22 regs, ~75% occupancy.

#define V8PT 2  // 8-float (32B) vectors per thread
#define TPB  256

__device__ __forceinline__ void ld256_evict_last(const float* p, unsigned* v) {
    asm volatile("ld.global.L2::evict_last.v8.b32 {%0,%1,%2,%3,%4,%5,%6,%7}, [%8];"
                 : "=r"(v[0]), "=r"(v[1]), "=r"(v[2]), "=r"(v[3]),
                   "=r"(v[4]), "=r"(v[5]), "=r"(v[6]), "=r"(v[7])
                 : "l"(p));
}

__device__ __forceinline__ void st256_evict_first(float* p, const unsigned* v) {
    asm volatile("st.global.L2::evict_first.v8.b32 [%0], {%1,%2,%3,%4,%5,%6,%7,%8};"
                 :: "l"(p),
                    "r"(v[0]), "r"(v[1]), "r"(v[2]), "r"(v[3]),
                    "r"(v[4]), "r"(v[5]), "r"(v[6]), "r"(v[7])
                 : "memory");
}

__device__ __forceinline__ void halve8(unsigned* v) {
    #pragma unroll
    for (int j = 0; j < 8; j++) {
        float f = __uint_as_float(v[j]);
        v[j] = __float_as_uint(floorf(f * 0.5f));
    }
}

__global__ void __launch_bounds__(TPB) stego_halve_kernel(
    const float* __restrict__ in, float* __restrict__ out, int n8)
{
    int blockBase = blockIdx.x * (TPB * V8PT);   // in v8 units
    int t = threadIdx.x;

    if (blockBase + TPB * V8PT <= n8) {
        unsigned v[V8PT][8];
        #pragma unroll
        for (int k = 0; k < V8PT; k++)
            ld256_evict_last(in + (size_t)(blockBase + t + k * TPB) * 8, v[k]);
        #pragma unroll
        for (int k = 0; k < V8PT; k++) {
            halve8(v[k]);
            st256_evict_first(out + (size_t)(blockBase + t + k * TPB) * 8, v[k]);
        }
    } else {
        // tail (unused for n = 25,165,824, but safe)
        #pragma unroll
        for (int k = 0; k < V8PT; k++) {
            int i = blockBase + t + k * TPB;
            if (i < n8) {
                unsigned v[8];
                ld256_evict_last(in + (size_t)i * 8, v);
                halve8(v);
                st256_evict_first(out + (size_t)i * 8, v);
            }
        }
    }
}

extern "C" void kernel_launch(void* const* d_in, const int* in_sizes, int n_in,
                              void* d_out, int out_size)
{
    const float* img = (const float*)d_in[0];
    float* out = (float*)d_out;
    int n = in_sizes[0];                 // 25,165,824 — divisible by 8
    int n8 = n / 8;
    int elems_per_block = TPB * V8PT;
    int blocks = (n8 + elems_per_block - 1) / elems_per_block;
    stego_halve_kernel<<<blocks, TPB>>>(img, out, n8);
}